// round 2
// baseline (speedup 1.0000x reference)
#include <cuda_runtime.h>
#include <cstdint>
#include <cstddef>

#define BATCH 128
#define TSTEPS 2048
#define INSZ 128
#define HID 256
#define OUTSZ 64
#define GIN 192
#define NBLK 128
#define NTHR 256
#define HS_STRIDE 260
#define XS_STRIDE 132

typedef unsigned long long ull;

__device__ float g_h[2][BATCH * HID];     // h ping-pong, [b][k]
__device__ float g_yT[2][OUTSZ * BATCH];  // y ping-pong, transposed [o][b]
__device__ unsigned g_hflag[NBLK];
__device__ unsigned g_yflag[NBLK];

__device__ __forceinline__ ull ffma2(ull a, ull b, ull c) {
    ull d; asm("fma.rn.f32x2 %0, %1, %2, %3;" : "=l"(d) : "l"(a), "l"(b), "l"(c));
    return d;
}
__device__ __forceinline__ ull packf2(float lo, float hi) {
    ull r; asm("mov.b64 %0, {%1, %2};" : "=l"(r) : "f"(lo), "f"(hi));
    return r;
}
__device__ __forceinline__ float sumf2(ull v) {
    float a, b; asm("mov.b64 {%0, %1}, %2;" : "=f"(a), "=f"(b) : "l"(v));
    return a + b;
}
__device__ __forceinline__ unsigned ld_acq(const unsigned* p) {
    unsigned v; asm volatile("ld.acquire.gpu.global.u32 %0, [%1];" : "=r"(v) : "l"(p));
    return v;
}
__device__ __forceinline__ void st_rel(unsigned* p, unsigned v) {
    asm volatile("st.release.gpu.global.u32 [%0], %1;" :: "l"(p), "r"(v));
}

__global__ void jordan_init_kernel() {
    const int stride = gridDim.x * blockDim.x;
    const int n = BATCH * HID + OUTSZ * BATCH + 2 * NBLK;
    for (int i = blockIdx.x * blockDim.x + threadIdx.x; i < n; i += stride) {
        if (i < BATCH * HID) g_h[0][i] = 0.0f;
        else if (i < BATCH * HID + OUTSZ * BATCH) g_yT[0][i - BATCH * HID] = 0.0f;
        else {
            int f = i - BATCH * HID - OUTSZ * BATCH;
            if (f < NBLK) g_hflag[f] = 0u; else g_yflag[f - NBLK] = 0u;
        }
    }
}

__global__ void __launch_bounds__(NTHR, 1) jordan_kernel(
    const float* __restrict__ x,      // [B, T, I]
    const float* __restrict__ w_ih,   // [3H, GIN]
    const float* __restrict__ w_hh,   // [3H, H]
    const float* __restrict__ b_ih,   // [3H]
    const float* __restrict__ b_hh,   // [3H]
    const float* __restrict__ fc_w,   // [O, H]
    const float* __restrict__ fc_b,   // [O]
    float* __restrict__ out)          // [B, O]
{
    extern __shared__ float sm[];
    float* h_s   = sm;                         // BATCH * 260
    float* x_s   = h_s + BATCH * HS_STRIDE;    // BATCH * 132
    float* wih_s = x_s + BATCH * XS_STRIDE;    // 6 * 192 (row = q*2+u)
    float* whh_s = wih_s + 6 * GIN;            // 6 * 256
    float* fc_s  = whh_s + 6 * HID;            // 256
    float* bih_s = fc_s + HID;                 // 8
    float* bhh_s = bih_s + 8;                  // 8

    const int g   = blockIdx.x;
    const int tid = threadIdx.x;
    const int b   = tid >> 1;
    const int u   = tid & 1;
    const int j0  = g * 2;
    const int orow  = g >> 1;
    const int bbase = (g & 1) * 64;

    for (int i = tid; i < 6 * GIN; i += NTHR) {
        int lr = i / GIN, k = i - lr * GIN;
        wih_s[i] = w_ih[(j0 + (lr & 1) + (lr >> 1) * HID) * GIN + k];
    }
    for (int i = tid; i < 6 * HID; i += NTHR) {
        int lr = i >> 8, k = i & 255;
        whh_s[i] = w_hh[(j0 + (lr & 1) + (lr >> 1) * HID) * HID + k];
    }
    for (int i = tid; i < HID; i += NTHR) fc_s[i] = fc_w[orow * HID + i];
    if (tid < 6) {
        bih_s[tid] = b_ih[j0 + (tid & 1) + (tid >> 1) * HID];
        bhh_s[tid] = b_hh[j0 + (tid & 1) + (tid >> 1) * HID];
    }
    const float fcb = fc_b[orow];
    __syncthreads();

    for (int t = 0; t < TSTEPS; t++) {
        const int cur = t & 1, nxt = cur ^ 1;

        // stage x_t (independent of recurrence)
        {
            const float4* xg = reinterpret_cast<const float4*>(x);
            for (int i = tid; i < BATCH * 32; i += NTHR) {
                int row = i >> 5, c = i & 31;
                float4 v = xg[((size_t)row * TSTEPS + t) * 32 + c];
                *reinterpret_cast<float4*>(x_s + row * XS_STRIDE + c * 4) = v;
            }
        }

        // wait for h_t from all blocks
        if (tid < NBLK) { while ((int)ld_acq(&g_hflag[tid]) < t) { } }
        __syncthreads();

        // stage h_t (coalesced) into padded smem
        {
            const float4* hg = reinterpret_cast<const float4*>(g_h[cur]);
            for (int i = tid; i < BATCH * 64; i += NTHR) {
                int row = i >> 6, c = i & 63;
                *reinterpret_cast<float4*>(h_s + row * HS_STRIDE + c * 4) = hg[row * 64 + c];
            }
        }
        __syncthreads();

        // y_t = tanh(h_t @ fc^T + fc_b), distributed (this block's piece)
        if (t > 0) {
            if (tid < 64) {
                const int bb = bbase + tid;
                const ulonglong2* hr = reinterpret_cast<const ulonglong2*>(h_s + bb * HS_STRIDE);
                const ulonglong2* fp = reinterpret_cast<const ulonglong2*>(fc_s);
                ull a0 = 0, a1 = 0;
                #pragma unroll 4
                for (int kk = 0; kk < 64; kk++) {
                    ulonglong2 hv = hr[kk], fv = fp[kk];
                    a0 = ffma2(hv.x, fv.x, a0);
                    a1 = ffma2(hv.y, fv.y, a1);
                }
                g_yT[cur][orow * BATCH + bb] = tanhf(sumf2(a0) + sumf2(a1) + fcb);
                __threadfence();
            }
            __syncthreads();
            if (tid == 0) st_rel(&g_yflag[g], (unsigned)t);
        }

        ull aRe = 0, aRo = 0, aZe = 0, aZo = 0;
        ull aNie = 0, aNio = 0, aNhe = 0, aNho = 0;

        // gh = h_t @ w_hh^T (big loop hides the y-flag latency)
        {
            const ulonglong2* hp = reinterpret_cast<const ulonglong2*>(h_s + b * HS_STRIDE);
            const ulonglong2* w0 = reinterpret_cast<const ulonglong2*>(whh_s + (0 * 2 + u) * HID);
            const ulonglong2* w1 = reinterpret_cast<const ulonglong2*>(whh_s + (1 * 2 + u) * HID);
            const ulonglong2* w2 = reinterpret_cast<const ulonglong2*>(whh_s + (2 * 2 + u) * HID);
            #pragma unroll 4
            for (int kk = 0; kk < 64; kk++) {
                ulonglong2 hv = hp[kk];
                ulonglong2 v0 = w0[kk];
                aRe = ffma2(hv.x, v0.x, aRe); aRo = ffma2(hv.y, v0.y, aRo);
                ulonglong2 v1 = w1[kk];
                aZe = ffma2(hv.x, v1.x, aZe); aZo = ffma2(hv.y, v1.y, aZo);
                ulonglong2 v2 = w2[kk];
                aNhe = ffma2(hv.x, v2.x, aNhe); aNho = ffma2(hv.y, v2.y, aNho);
            }
        }

        // gi_x = x_t @ w_ih[:, :128]^T
        {
            const ulonglong2* xp = reinterpret_cast<const ulonglong2*>(x_s + b * XS_STRIDE);
            const ulonglong2* w0 = reinterpret_cast<const ulonglong2*>(wih_s + (0 * 2 + u) * GIN);
            const ulonglong2* w1 = reinterpret_cast<const ulonglong2*>(wih_s + (1 * 2 + u) * GIN);
            const ulonglong2* w2 = reinterpret_cast<const ulonglong2*>(wih_s + (2 * 2 + u) * GIN);
            #pragma unroll 4
            for (int kk = 0; kk < 32; kk++) {
                ulonglong2 xv = xp[kk];
                ulonglong2 v0 = w0[kk];
                aRe = ffma2(xv.x, v0.x, aRe); aRo = ffma2(xv.y, v0.y, aRo);
                ulonglong2 v1 = w1[kk];
                aZe = ffma2(xv.x, v1.x, aZe); aZo = ffma2(xv.y, v1.y, aZo);
                ulonglong2 v2 = w2[kk];
                aNie = ffma2(xv.x, v2.x, aNie); aNio = ffma2(xv.y, v2.y, aNio);
            }
        }

        // wait for all blocks' y_t pieces (usually already set)
        if (tid < NBLK) { while ((int)ld_acq(&g_yflag[tid]) < t) { } }
        __syncthreads();

        // gi_y = y_t @ w_ih[:, 128:]^T (coalesced reads of y^T)
        {
            const float* yr = g_yT[cur];
            const ull* w0 = reinterpret_cast<const ull*>(wih_s + (0 * 2 + u) * GIN + INSZ);
            const ull* w1 = reinterpret_cast<const ull*>(wih_s + (1 * 2 + u) * GIN + INSZ);
            const ull* w2 = reinterpret_cast<const ull*>(wih_s + (2 * 2 + u) * GIN + INSZ);
            #pragma unroll 4
            for (int oo = 0; oo < 32; oo++) {
                float ya = yr[(2 * oo) * BATCH + b];
                float yb = yr[(2 * oo + 1) * BATCH + b];
                ull yp = packf2(ya, yb);
                aRe  = ffma2(yp, w0[oo], aRe);
                aZe  = ffma2(yp, w1[oo], aZe);
                aNie = ffma2(yp, w2[oo], aNie);
            }
        }

        // gates + state update
        float preR = sumf2(aRe) + sumf2(aRo) + bih_s[0 + u] + bhh_s[0 + u];
        float preZ = sumf2(aZe) + sumf2(aZo) + bih_s[2 + u] + bhh_s[2 + u];
        float giN  = sumf2(aNie) + sumf2(aNio) + bih_s[4 + u];
        float ghN  = sumf2(aNhe) + sumf2(aNho) + bhh_s[4 + u];
        float r = 1.0f / (1.0f + __expf(-preR));
        float z = 1.0f / (1.0f + __expf(-preZ));
        float n = tanhf(giN + r * ghN);
        float hprev = h_s[b * HS_STRIDE + j0 + u];
        float hnew = (1.0f - z) * n + z * hprev;
        g_h[nxt][b * HID + j0 + u] = hnew;

        __threadfence();
        __syncthreads();
        if (tid == 0) st_rel(&g_hflag[g], (unsigned)(t + 1));
    }

    // final output: y_T = tanh(h_T @ fc^T + fc_b), h_T in g_h[0] (T even)
    if (tid < NBLK) { while ((int)ld_acq(&g_hflag[tid]) < TSTEPS) { } }
    __syncthreads();
    if (tid < 64) {
        const int bb = bbase + tid;
        const float4* hr = reinterpret_cast<const float4*>(g_h[0] + bb * HID);
        const float4* fp = reinterpret_cast<const float4*>(fc_s);
        float acc = fcb;
        #pragma unroll 4
        for (int kk = 0; kk < 64; kk++) {
            float4 hv = hr[kk], fv = fp[kk];
            acc += hv.x * fv.x + hv.y * fv.y + hv.z * fv.z + hv.w * fv.w;
        }
        out[bb * OUTSZ + orow] = tanhf(acc);
    }
}

extern "C" void kernel_launch(void* const* d_in, const int* in_sizes, int n_in,
                              void* d_out, int out_size) {
    (void)in_sizes; (void)n_in; (void)out_size;
    const float* x    = (const float*)d_in[0];
    const float* w_ih = (const float*)d_in[1];
    const float* w_hh = (const float*)d_in[2];
    const float* b_ih = (const float*)d_in[3];
    const float* b_hh = (const float*)d_in[4];
    const float* fc_w = (const float*)d_in[5];
    const float* fc_b = (const float*)d_in[6];
    float* out = (float*)d_out;

    const int smem_floats = BATCH * HS_STRIDE + BATCH * XS_STRIDE +
                            6 * GIN + 6 * HID + HID + 16;
    const int smem_bytes = smem_floats * (int)sizeof(float); // 212,608 B

    static int configured = 0;
    if (!configured) {
        cudaFuncSetAttribute(jordan_kernel,
                             cudaFuncAttributeMaxDynamicSharedMemorySize,
                             smem_bytes);
        configured = 1;
    }

    jordan_init_kernel<<<64, 256>>>();
    jordan_kernel<<<NBLK, NTHR, smem_bytes>>>(x, w_ih, w_hh, b_ih, b_hh,
                                              fc_w, fc_b, out);
}

// round 3
// speedup vs baseline: 1.8012x; 1.8012x over previous
#include <cuda_runtime.h>
#include <cstdint>
#include <cstddef>

// Jordan GRU, B=128, T=2048, I=128, H=256, O=64.
// Partition: 16 groups x 8 slices. Block = 8 batch rows x 32 hidden units.
// Only group-local (8-block) exchange of h (8KB) and y (2KB) per step.

#define BATCH 128
#define TSTEPS 2048
#define INSZ 128
#define HID 256
#define OUTSZ 64
#define GIN 192
#define NBLK 128
#define NTHR 256

#define ROWS 8          // batch rows per block
#define UNITS 32        // hidden units per block
#define NSLICE 8
#define NGROUP 16

// padded smem strides (floats)
#define HS 260          // h rows      (mod 32 = 4 -> 8 rows cover all banks)
#define XS 132          // x rows      (mod 32 = 4)
#define YS 68           // y rows      (mod 32 = 4)
#define WHS 264         // w_hh rows   (mod 32 = 8 -> 4 rows bank-disjoint)
#define WIS 200         // w_ih rows   (mod 32 = 8)
#define FCS 264         // fc rows

typedef unsigned long long ull;

__device__ float g_h[2][BATCH * HID];   // [b][k]
__device__ float g_y[2][BATCH * OUTSZ]; // [b][o]
__device__ unsigned g_hflag[NBLK];
__device__ unsigned g_yflag[NBLK];

__device__ __forceinline__ ull ffma2(ull a, ull b, ull c) {
    ull d; asm("fma.rn.f32x2 %0, %1, %2, %3;" : "=l"(d) : "l"(a), "l"(b), "l"(c));
    return d;
}
__device__ __forceinline__ float sumf2(ull v) {
    float a, b; asm("mov.b64 {%0, %1}, %2;" : "=f"(a), "=f"(b) : "l"(v));
    return a + b;
}
__device__ __forceinline__ unsigned ld_acq(const unsigned* p) {
    unsigned v; asm volatile("ld.acquire.gpu.global.u32 %0, [%1];" : "=r"(v) : "l"(p));
    return v;
}
__device__ __forceinline__ void st_rel(unsigned* p, unsigned v) {
    asm volatile("st.release.gpu.global.u32 [%0], %1;" :: "l"(p), "r"(v));
}

__global__ void jordan_init_kernel() {
    const int stride = gridDim.x * blockDim.x;
    const int n = BATCH * HID + BATCH * OUTSZ + 2 * NBLK;
    for (int i = blockIdx.x * blockDim.x + threadIdx.x; i < n; i += stride) {
        if (i < BATCH * HID) g_h[0][i] = 0.0f;
        else if (i < BATCH * HID + BATCH * OUTSZ) g_y[0][i - BATCH * HID] = 0.0f;
        else {
            int f = i - BATCH * HID - BATCH * OUTSZ;
            if (f < NBLK) g_hflag[f] = 0u; else g_yflag[f - NBLK] = 0u;
        }
    }
}

__global__ void __launch_bounds__(NTHR, 1) jordan_kernel(
    const float* __restrict__ x,      // [B, T, I]
    const float* __restrict__ w_ih,   // [3H, GIN]
    const float* __restrict__ w_hh,   // [3H, H]
    const float* __restrict__ b_ih,   // [3H]
    const float* __restrict__ b_hh,   // [3H]
    const float* __restrict__ fc_w,   // [O, H]
    const float* __restrict__ fc_b,   // [O]
    float* __restrict__ out)          // [B, O]
{
    extern __shared__ float sm[];
    float* h_s   = sm;                        // 8 * 260   = 2080
    float* x_s   = h_s + ROWS * HS;           // 8 * 132   = 1056
    float* y_s   = x_s + ROWS * XS;           // 8 * 68    = 544
    float* whh_s = y_s + ROWS * YS;           // 96 * 264  = 25344 (row = gate*32+u)
    float* wih_s = whh_s + 96 * WHS;          // 96 * 200  = 19200
    float* fc_s  = wih_s + 96 * WIS;          // 8 * 264   = 2112
    float* bih_s = fc_s + 8 * FCS;            // 96
    float* bhh_s = bih_s + 96;                // 96
    float* fcb_s = bhh_s + 96;                // 8

    const int tid   = threadIdx.x;
    const int lane  = tid & 31;
    const int warp  = tid >> 5;
    const int b     = lane & 7;               // local batch row 0..7
    const int unit  = warp * 4 + (lane >> 3); // local hidden unit 0..31

    const int blk   = blockIdx.x;
    const int group = blk >> 3;               // 0..15
    const int slice = blk & 7;                // 0..7
    const int b0    = group * ROWS;           // first global batch row
    const int fbase = group * NSLICE;         // first flag index of this group

    // ---- load weights / biases into smem ----
    for (int i = tid; i < 96 * HID; i += NTHR) {
        int row = i >> 8, k = i & 255;                       // row = gate*32 + u
        int grow = (row >> 5) * HID + slice * UNITS + (row & 31);
        whh_s[row * WHS + k] = w_hh[grow * HID + k];
    }
    for (int i = tid; i < 96 * GIN; i += NTHR) {
        int row = i / GIN, k = i - row * GIN;
        int grow = (row >> 5) * HID + slice * UNITS + (row & 31);
        wih_s[row * WIS + k] = w_ih[grow * GIN + k];
    }
    for (int i = tid; i < 8 * HID; i += NTHR) {
        int r = i >> 8, k = i & 255;
        fc_s[r * FCS + k] = fc_w[(slice * 8 + r) * HID + k];
    }
    if (tid < 96) {
        int grow = (tid >> 5) * HID + slice * UNITS + (tid & 31);
        bih_s[tid] = b_ih[grow];
        bhh_s[tid] = b_hh[grow];
    }
    if (tid < 8) fcb_s[tid] = fc_b[slice * 8 + tid];
    __syncthreads();

    // pre-computed smem pointers
    const float* hrow  = h_s + b * HS;
    const float* xrow  = x_s + b * XS;
    const float* yrow  = y_s + b * YS;
    const float* whR   = whh_s + (0 * UNITS + unit) * WHS;
    const float* whZ   = whh_s + (1 * UNITS + unit) * WHS;
    const float* whN   = whh_s + (2 * UNITS + unit) * WHS;
    const float* wiR   = wih_s + (0 * UNITS + unit) * WIS;
    const float* wiZ   = wih_s + (1 * UNITS + unit) * WIS;
    const float* wiN   = wih_s + (2 * UNITS + unit) * WIS;

    for (int t = 0; t < TSTEPS; t++) {
        const int cur = t & 1, nxt = cur ^ 1;

        // ---- stage x_t (independent of recurrence; overlaps flag wait) ----
        if (tid < ROWS * 32) {                    // 8 rows * 32 float4
            int row = tid >> 5, c = tid & 31;
            float4 v = reinterpret_cast<const float4*>(x)
                           [((size_t)(b0 + row) * TSTEPS + t) * 32 + c];
            *reinterpret_cast<float4*>(x_s + row * XS + c * 4) = v;
        }

        // ---- wait for h_t from group siblings ----
        if (tid < NSLICE) { while ((int)ld_acq(&g_hflag[fbase + tid]) < t) { } }
        __syncthreads();

        // ---- stage h_t (8 rows, 8KB) ----
        {
            const float4* hg = reinterpret_cast<const float4*>(g_h[cur]);
            for (int i = tid; i < ROWS * 64; i += NTHR) {
                int row = i >> 6, c = i & 63;
                *reinterpret_cast<float4*>(h_s + row * HS + c * 4) =
                    hg[(b0 + row) * 64 + c];
            }
        }
        __syncthreads();

        // ---- y_t piece: this block's 8 outputs for its 8 rows ----
        if (t > 0) {
            if (tid < 64) {
                const int yb = tid & 7, ol = tid >> 3;
                const ulonglong2* hp = reinterpret_cast<const ulonglong2*>(h_s + yb * HS);
                const ulonglong2* fp = reinterpret_cast<const ulonglong2*>(fc_s + ol * FCS);
                ull a0 = 0, a1 = 0;
                #pragma unroll 8
                for (int c = 0; c < 64; c++) {
                    ulonglong2 hv = hp[c], fv = fp[c];
                    a0 = ffma2(hv.x, fv.x, a0);
                    a1 = ffma2(hv.y, fv.y, a1);
                }
                g_y[cur][(b0 + yb) * OUTSZ + slice * 8 + ol] =
                    tanhf(sumf2(a0) + sumf2(a1) + fcb_s[ol]);
                __threadfence();
            }
            __syncthreads();
            if (tid == 0) st_rel(&g_yflag[blk], (unsigned)t);
        }

        ull aRe = 0, aRo = 0, aZe = 0, aZo = 0;
        ull aNie = 0, aNio = 0, aNhe = 0, aNho = 0;

        // ---- gh = h_t @ w_hh^T (hides y flag latency) ----
        {
            const ulonglong2* hp = reinterpret_cast<const ulonglong2*>(hrow);
            const ulonglong2* r0 = reinterpret_cast<const ulonglong2*>(whR);
            const ulonglong2* r1 = reinterpret_cast<const ulonglong2*>(whZ);
            const ulonglong2* r2 = reinterpret_cast<const ulonglong2*>(whN);
            #pragma unroll 8
            for (int c = 0; c < 64; c++) {
                ulonglong2 hv = hp[c];
                ulonglong2 v0 = r0[c];
                aRe = ffma2(hv.x, v0.x, aRe); aRo = ffma2(hv.y, v0.y, aRo);
                ulonglong2 v1 = r1[c];
                aZe = ffma2(hv.x, v1.x, aZe); aZo = ffma2(hv.y, v1.y, aZo);
                ulonglong2 v2 = r2[c];
                aNhe = ffma2(hv.x, v2.x, aNhe); aNho = ffma2(hv.y, v2.y, aNho);
            }
        }

        // ---- gi_x = x_t part ----
        {
            const ulonglong2* xp = reinterpret_cast<const ulonglong2*>(xrow);
            const ulonglong2* r0 = reinterpret_cast<const ulonglong2*>(wiR);
            const ulonglong2* r1 = reinterpret_cast<const ulonglong2*>(wiZ);
            const ulonglong2* r2 = reinterpret_cast<const ulonglong2*>(wiN);
            #pragma unroll 8
            for (int c = 0; c < 32; c++) {
                ulonglong2 xv = xp[c];
                ulonglong2 v0 = r0[c];
                aRe = ffma2(xv.x, v0.x, aRe); aRo = ffma2(xv.y, v0.y, aRo);
                ulonglong2 v1 = r1[c];
                aZe = ffma2(xv.x, v1.x, aZe); aZo = ffma2(xv.y, v1.y, aZo);
                ulonglong2 v2 = r2[c];
                aNie = ffma2(xv.x, v2.x, aNie); aNio = ffma2(xv.y, v2.y, aNio);
            }
        }

        // ---- wait for siblings' y pieces, stage y (8 rows x 64) ----
        if (tid < NSLICE) { while ((int)ld_acq(&g_yflag[fbase + tid]) < t) { } }
        __syncthreads();
        if (tid < ROWS * 16) {                    // 8 rows * 16 float4
            int row = tid >> 4, c = tid & 15;
            float4 v = reinterpret_cast<const float4*>(g_y[cur])
                           [(b0 + row) * 16 + c];
            *reinterpret_cast<float4*>(y_s + row * YS + c * 4) = v;
        }
        __syncthreads();

        // ---- gi_y = y_t part ----
        {
            const ulonglong2* yp = reinterpret_cast<const ulonglong2*>(yrow);
            const ulonglong2* r0 = reinterpret_cast<const ulonglong2*>(wiR + INSZ);
            const ulonglong2* r1 = reinterpret_cast<const ulonglong2*>(wiZ + INSZ);
            const ulonglong2* r2 = reinterpret_cast<const ulonglong2*>(wiN + INSZ);
            #pragma unroll
            for (int c = 0; c < 16; c++) {
                ulonglong2 yv = yp[c];
                ulonglong2 v0 = r0[c];
                aRe = ffma2(yv.x, v0.x, aRe); aRo = ffma2(yv.y, v0.y, aRo);
                ulonglong2 v1 = r1[c];
                aZe = ffma2(yv.x, v1.x, aZe); aZo = ffma2(yv.y, v1.y, aZo);
                ulonglong2 v2 = r2[c];
                aNie = ffma2(yv.x, v2.x, aNie); aNio = ffma2(yv.y, v2.y, aNio);
            }
        }

        // ---- gates + state update ----
        float preR = sumf2(aRe) + sumf2(aRo) + bih_s[unit]      + bhh_s[unit];
        float preZ = sumf2(aZe) + sumf2(aZo) + bih_s[32 + unit] + bhh_s[32 + unit];
        float giN  = sumf2(aNie) + sumf2(aNio) + bih_s[64 + unit];
        float ghN  = sumf2(aNhe) + sumf2(aNho) + bhh_s[64 + unit];
        float r = 1.0f / (1.0f + __expf(-preR));
        float z = 1.0f / (1.0f + __expf(-preZ));
        float n = tanhf(giN + r * ghN);
        float hprev = hrow[slice * UNITS + unit];
        float hnew = (1.0f - z) * n + z * hprev;
        g_h[nxt][(b0 + b) * HID + slice * UNITS + unit] = hnew;

        __threadfence();
        __syncthreads();
        if (tid == 0) st_rel(&g_hflag[blk], (unsigned)(t + 1));
    }

    // ---- final output: y_T = tanh(fc(h_T)); h_T in g_h[0] (T even) ----
    if (tid < NSLICE) { while ((int)ld_acq(&g_hflag[fbase + tid]) < TSTEPS) { } }
    __syncthreads();
    {
        const float4* hg = reinterpret_cast<const float4*>(g_h[0]);
        for (int i = tid; i < ROWS * 64; i += NTHR) {
            int row = i >> 6, c = i & 63;
            *reinterpret_cast<float4*>(h_s + row * HS + c * 4) = hg[(b0 + row) * 64 + c];
        }
    }
    __syncthreads();
    if (tid < 64) {
        const int yb = tid & 7, ol = tid >> 3;
        const ulonglong2* hp = reinterpret_cast<const ulonglong2*>(h_s + yb * HS);
        const ulonglong2* fp = reinterpret_cast<const ulonglong2*>(fc_s + ol * FCS);
        ull a0 = 0, a1 = 0;
        #pragma unroll 8
        for (int c = 0; c < 64; c++) {
            ulonglong2 hv = hp[c], fv = fp[c];
            a0 = ffma2(hv.x, fv.x, a0);
            a1 = ffma2(hv.y, fv.y, a1);
        }
        out[(b0 + yb) * OUTSZ + slice * 8 + ol] =
            tanhf(sumf2(a0) + sumf2(a1) + fcb_s[ol]);
    }
}

extern "C" void kernel_launch(void* const* d_in, const int* in_sizes, int n_in,
                              void* d_out, int out_size) {
    (void)in_sizes; (void)n_in; (void)out_size;
    const float* x    = (const float*)d_in[0];
    const float* w_ih = (const float*)d_in[1];
    const float* w_hh = (const float*)d_in[2];
    const float* b_ih = (const float*)d_in[3];
    const float* b_hh = (const float*)d_in[4];
    const float* fc_w = (const float*)d_in[5];
    const float* fc_b = (const float*)d_in[6];
    float* out = (float*)d_out;

    const int smem_floats = ROWS * HS + ROWS * XS + ROWS * YS +
                            96 * WHS + 96 * WIS + 8 * FCS + 96 + 96 + 8 + 8;
    const int smem_bytes = smem_floats * (int)sizeof(float); // ~202 KB

    cudaFuncSetAttribute(jordan_kernel,
                         cudaFuncAttributeMaxDynamicSharedMemorySize,
                         smem_bytes);

    jordan_init_kernel<<<64, 256>>>();
    jordan_kernel<<<NBLK, NTHR, smem_bytes>>>(x, w_ih, w_hh, b_ih, b_hh,
                                              fc_w, fc_b, out);
}